// round 15
// baseline (speedup 1.0000x reference)
#include <cuda_runtime.h>
#include <cuda_bf16.h>
#include <math.h>
#include <stdint.h>

// Problem constants (fixed: B=4096, D=1024)
#define BDIM 4096
#define DDIM 1024
#define INV_T 20.0f
#define NBLK 32                 // BDIM / 128 block-columns
#define KT 128                  // fp8 k elements per stage (128 B rows, swizzled)
#define NK (DDIM / KT)          // 8 k-tiles
#define NSTG 3                  // pipeline stages
#define STG_BYTES (2 * 128 * 128)            // A+B per stage = 32768 B
#define DSMEM (NSTG * STG_BYTES)             // 98304 B dynamic smem
#define INV_S2 (1.0f / 8192.0f)              // 2 / (128*128)

// Deterministic scratch (atomics only on an int completion counter)
__device__ float g_img_sq[BDIM];
__device__ float g_txt_sq[BDIM];
__device__ float g_diag[BDIM];
__device__ float g_part[BDIM][NBLK];
__device__ float g_losspart[32];
__device__ int   g_cnt;
__device__ uint8_t g_A8[(size_t)BDIM * DDIM];   // image, e4m3 (x128)
__device__ uint8_t g_B8[(size_t)BDIM * DDIM];   // text,  e4m3 (x128)

// ---------------------------------------------------------------------------
// Fast epilogue math: sim = exp(-T^-1 * sqrt(max(q,0))) with single-MUFU
// sqrt.approx (rel err ~1e-7, negligible vs fp8 path's 3e-5).
// ---------------------------------------------------------------------------
__device__ __forceinline__ float sim_of(float q) {
    float d;
    asm("sqrt.approx.f32 %0, %1;" : "=f"(d) : "f"(fmaxf(q, 0.0f)));
    return __expf(-INV_T * d);
}

// ---------------------------------------------------------------------------
// Kernel 1: fp32 -> e4m3 (scaled by 128) + fp32 exact squared norms.
// One row per warp (best measured variant). grid = (BDIM/8, 2), 256 threads.
// ---------------------------------------------------------------------------
__device__ __forceinline__ uint16_t f2_to_e4m3x2(float hi, float lo) {
    uint16_t d;
    asm("cvt.rn.satfinite.e4m3x2.f32 %0, %1, %2;" : "=h"(d) : "f"(hi), "f"(lo));
    return d;
}

__global__ void convert_norms_kernel(const float* __restrict__ img,
                                     const float* __restrict__ txt) {
    const int warp = threadIdx.x >> 5, lane = threadIdx.x & 31;
    const int row  = blockIdx.x * 8 + warp;
    const float* src;
    uint8_t* dst;
    float* nrm;
    if (blockIdx.y == 0) { src = img; dst = g_A8; nrm = g_img_sq; }
    else                 { src = txt; dst = g_B8; nrm = g_txt_sq; }

    const float4* p = reinterpret_cast<const float4*>(src + (size_t)row * DDIM);
    uint32_t* q = reinterpret_cast<uint32_t*>(dst + (size_t)row * DDIM);

    float s = 0.0f;
    #pragma unroll
    for (int i = 0; i < 8; i++) {
        int f = i * 32 + lane;
        float4 v = p[f];
        s += v.x * v.x + v.y * v.y + v.z * v.z + v.w * v.w;
        uint16_t lo = f2_to_e4m3x2(v.y * 128.0f, v.x * 128.0f);
        uint16_t hi = f2_to_e4m3x2(v.w * 128.0f, v.z * 128.0f);
        q[f] = (uint32_t)lo | ((uint32_t)hi << 16);
    }
    #pragma unroll
    for (int m = 16; m > 0; m >>= 1) s += __shfl_xor_sync(0xffffffffu, s, m);
    if (lane == 0) nrm[row] = s;
}

// ---------------------------------------------------------------------------
// Kernel 2: e4m3 mma.sync m16n8k32 GEMM. 128x128 CTA tile, 4 warps of
// 64x64, KT=128, 3-stage cp.async pipeline, XOR-swizzled 128B rows.
// load_stage is NOT unrolled: addresses are recomputed per iteration so
// ~48 address registers are not pinned live across the mainloop
// (regs were capped at 255 -> local-memory spills in the hot loop).
// ---------------------------------------------------------------------------
__device__ __forceinline__ void load_stage(uint8_t* smem, int stage,
                                           int kt, int row0, int col0, int tid) {
    uint8_t* as = smem + (size_t)stage * STG_BYTES;
    uint8_t* bs = as + 128 * 128;
    #pragma unroll 1
    for (int l = 0; l < 8; l++) {
        const int id = tid + l * 128;        // 0..1023
        const int r  = id >> 3;              // tile row 0..127
        const int ch = id & 7;               // logical 16B chunk 0..7
        const int ph = ch ^ (r & 7);         // swizzled chunk
        uint32_t da = (uint32_t)__cvta_generic_to_shared(&as[r * 128 + ph * 16]);
        const void* ga = g_A8 + (size_t)(row0 + r) * DDIM + kt + ch * 16;
        asm volatile("cp.async.cg.shared.global [%0], [%1], 16;\n"
                     :: "r"(da), "l"(ga));
        uint32_t db = (uint32_t)__cvta_generic_to_shared(&bs[r * 128 + ph * 16]);
        const void* gb = g_B8 + (size_t)(col0 + r) * DDIM + kt + ch * 16;
        asm volatile("cp.async.cg.shared.global [%0], [%1], 16;\n"
                     :: "r"(db), "l"(gb));
    }
    asm volatile("cp.async.commit_group;\n" ::: "memory");
}

__global__ __launch_bounds__(128, 2)
void mma_sim_kernel() {
    extern __shared__ uint8_t smem[];
    __shared__ float s_isq[128];
    __shared__ float s_tsq[128];
    __shared__ float red[128][2];

    const int bj = blockIdx.x;
    const int bi = blockIdx.y;
    const int row0 = bi * 128;
    const int col0 = bj * 128;

    const int tid  = threadIdx.x;         // 0..127
    const int lane = tid & 31;
    const int warp = tid >> 5;            // 0..3
    const int wm   = warp >> 1;           // 0..1 (m)
    const int wn   = warp & 1;            // 0..1 (n)

    s_isq[tid] = g_img_sq[row0 + tid];
    s_tsq[tid] = g_txt_sq[col0 + tid];

    float acc[4][8][4];
    #pragma unroll
    for (int mf = 0; mf < 4; mf++)
        #pragma unroll
        for (int nf = 0; nf < 8; nf++)
            #pragma unroll
            for (int r = 0; r < 4; r++) acc[mf][nf][r] = 0.0f;

    // Prologue: fill 2 of 3 stages
    load_stage(smem, 0, 0, row0, col0, tid);
    load_stage(smem, 1, KT, row0, col0, tid);

    const int a_row = wm * 64 + (lane & 15);
    const int a_ch0 = (lane >> 4);
    const int b_row = wn * 64 + ((lane >> 4) << 3) + (lane & 7);
    const int b_ch0 = ((lane >> 3) & 1);

    int stg = 0;
    for (int it = 0; it < NK; it++) {
        if (it + 2 < NK)
            asm volatile("cp.async.wait_group 1;\n" ::: "memory");
        else
            asm volatile("cp.async.wait_group 0;\n" ::: "memory");
        __syncthreads();

        if (it + 2 < NK) {
            int nstg = stg + 2; if (nstg >= NSTG) nstg -= NSTG;
            load_stage(smem, nstg, (it + 2) * KT, row0, col0, tid);
        }

        const uint8_t* as = smem + (size_t)stg * STG_BYTES;
        const uint8_t* bs = as + 128 * 128;

        #pragma unroll
        for (int ks = 0; ks < 4; ks++) {      // four k32 steps per 128-fp8 stage
            uint32_t a[4][4], b[4][4];
            #pragma unroll
            for (int mf = 0; mf < 4; mf++) {
                int r  = a_row + mf * 16;
                int ph = (a_ch0 + ks * 2) ^ (r & 7);
                uint32_t addr = (uint32_t)__cvta_generic_to_shared(
                    &as[r * 128 + ph * 16]);
                asm volatile(
                    "ldmatrix.sync.aligned.m8n8.x4.shared.b16 "
                    "{%0,%1,%2,%3}, [%4];\n"
                    : "=r"(a[mf][0]), "=r"(a[mf][1]),
                      "=r"(a[mf][2]), "=r"(a[mf][3])
                    : "r"(addr));
            }
            #pragma unroll
            for (int p = 0; p < 4; p++) {
                int n  = b_row + p * 16;
                int ph = (b_ch0 + ks * 2) ^ (n & 7);
                uint32_t addr = (uint32_t)__cvta_generic_to_shared(
                    &bs[n * 128 + ph * 16]);
                asm volatile(
                    "ldmatrix.sync.aligned.m8n8.x4.shared.b16 "
                    "{%0,%1,%2,%3}, [%4];\n"
                    : "=r"(b[p][0]), "=r"(b[p][1]),
                      "=r"(b[p][2]), "=r"(b[p][3])
                    : "r"(addr));
            }
            #pragma unroll
            for (int mf = 0; mf < 4; mf++) {
                #pragma unroll
                for (int nf = 0; nf < 8; nf++) {
                    uint32_t b0 = b[nf >> 1][(nf & 1) * 2];
                    uint32_t b1 = b[nf >> 1][(nf & 1) * 2 + 1];
                    asm volatile(
                        "mma.sync.aligned.m16n8k32.row.col.f32.e4m3.e4m3.f32 "
                        "{%0,%1,%2,%3},{%4,%5,%6,%7},{%8,%9},{%0,%1,%2,%3};\n"
                        : "+f"(acc[mf][nf][0]), "+f"(acc[mf][nf][1]),
                          "+f"(acc[mf][nf][2]), "+f"(acc[mf][nf][3])
                        : "r"(a[mf][0]), "r"(a[mf][1]),
                          "r"(a[mf][2]), "r"(a[mf][3]),
                          "r"(b0), "r"(b1));
                }
            }
        }
        if (++stg >= NSTG) stg = 0;
    }

    // ---- fused epilogue: sim -> row partial sums + diagonal ----
    const bool diagblk = (bi == bj);
    #pragma unroll
    for (int mf = 0; mf < 4; mf++) {
        const int r_lo = wm * 64 + mf * 16 + (lane >> 2);
        const int r_hi = r_lo + 8;
        const float ia = s_isq[r_lo];
        const float ib = s_isq[r_hi];
        float s_lo = 0.0f, s_hi = 0.0f;

        #pragma unroll
        for (int nf = 0; nf < 8; nf++) {
            const int c0 = wn * 64 + nf * 8 + (lane & 3) * 2;
            const float t0 = s_tsq[c0];
            const float t1 = s_tsq[c0 + 1];
            float e00 = sim_of(fmaf(acc[mf][nf][0], -INV_S2, ia + t0));
            float e01 = sim_of(fmaf(acc[mf][nf][1], -INV_S2, ia + t1));
            float e10 = sim_of(fmaf(acc[mf][nf][2], -INV_S2, ib + t0));
            float e11 = sim_of(fmaf(acc[mf][nf][3], -INV_S2, ib + t1));
            s_lo += e00 + e01;
            s_hi += e10 + e11;
            if (diagblk) {
                if (r_lo == c0)     g_diag[row0 + r_lo] = e00;
                if (r_lo == c0 + 1) g_diag[row0 + r_lo] = e01;
                if (r_hi == c0)     g_diag[row0 + r_hi] = e10;
                if (r_hi == c0 + 1) g_diag[row0 + r_hi] = e11;
            }
        }
        s_lo += __shfl_xor_sync(0xffffffffu, s_lo, 1);
        s_lo += __shfl_xor_sync(0xffffffffu, s_lo, 2);
        s_hi += __shfl_xor_sync(0xffffffffu, s_hi, 1);
        s_hi += __shfl_xor_sync(0xffffffffu, s_hi, 2);
        if ((lane & 3) == 0) {
            red[r_lo][wn] = s_lo;
            red[r_hi][wn] = s_hi;
        }
    }
    __syncthreads();
    g_part[row0 + tid][bj] = red[tid][0] + red[tid][1];
}

// ---------------------------------------------------------------------------
// Kernel 3: fused loss. 32 blocks x 128 rows compute partials; the LAST
// block to finish (int counter only; all float sums fixed-order) reduces
// the 32 partials, writes output, resets counter for graph replay.
// ---------------------------------------------------------------------------
__global__ void loss_kernel(float* __restrict__ out) {
    const int tid = threadIdx.x;   // 128 threads
    const int row = blockIdx.x * 128 + tid;

    const float4* pr = reinterpret_cast<const float4*>(&g_part[row][0]);
    float rowsum = 0.0f;
    #pragma unroll
    for (int b = 0; b < NBLK / 4; b++) {
        float4 v = pr[b];
        rowsum += v.x + v.y + v.z + v.w;
    }
    float num = g_diag[row];
    float den = rowsum - num;
    float s = (den != 0.0f) ? (logf(den) - logf(num)) : 0.0f;

    #pragma unroll
    for (int m = 16; m > 0; m >>= 1) s += __shfl_xor_sync(0xffffffffu, s, m);
    __shared__ float red[4];
    __shared__ int s_last;
    if ((tid & 31) == 0) red[tid >> 5] = s;
    __syncthreads();
    if (tid == 0) {
        g_losspart[blockIdx.x] = red[0] + red[1] + red[2] + red[3];
        __threadfence();
        s_last = (atomicAdd(&g_cnt, 1) == 31);
    }
    __syncthreads();
    if (s_last && tid < 32) {
        float t = g_losspart[tid];
        #pragma unroll
        for (int m = 16; m > 0; m >>= 1) t += __shfl_xor_sync(0xffffffffu, t, m);
        if (tid == 0) { out[0] = t / (float)BDIM; g_cnt = 0; }
    }
}

// ---------------------------------------------------------------------------
// Launch. Inputs: d_in[0] = text_embeddings, d_in[1] = image_embeddings.
// ---------------------------------------------------------------------------
extern "C" void kernel_launch(void* const* d_in, const int* in_sizes, int n_in,
                              void* d_out, int out_size) {
    const float* txt = (const float*)d_in[0];
    const float* img = (const float*)d_in[1];
    float* out = (float*)d_out;

    cudaFuncSetAttribute(mma_sim_kernel,
                         cudaFuncAttributeMaxDynamicSharedMemorySize, DSMEM);

    dim3 cgrid(BDIM / 8, 2);
    convert_norms_kernel<<<cgrid, 256>>>(img, txt);

    dim3 ggrid(NBLK, NBLK);
    mma_sim_kernel<<<ggrid, 128, DSMEM>>>();

    loss_kernel<<<32, 128>>>(out);
}

// round 16
// speedup vs baseline: 1.0184x; 1.0184x over previous
#include <cuda_runtime.h>
#include <cuda_bf16.h>
#include <math.h>
#include <stdint.h>

// Problem constants (fixed: B=4096, D=1024)
#define BDIM 4096
#define DDIM 1024
#define INV_T 20.0f
#define NBLK 32                 // BDIM / 128 block-columns
#define KT 128                  // fp8 k elements per stage (128 B rows, swizzled)
#define NK (DDIM / KT)          // 8 k-tiles
#define NSTG 3                  // pipeline stages
#define STG_BYTES (2 * 128 * 128)            // A+B per stage = 32768 B
#define DSMEM (NSTG * STG_BYTES)             // 98304 B dynamic smem
#define INV_S2 (1.0f / 8192.0f)              // 2 / (128*128)

// Deterministic scratch (atomics only on an int completion counter)
__device__ float g_img_sq[BDIM];
__device__ float g_txt_sq[BDIM];
__device__ float g_diag[BDIM];
__device__ float g_part[BDIM][NBLK];
__device__ float g_losspart[32];
__device__ int   g_cnt;
__device__ uint8_t g_A8[(size_t)BDIM * DDIM];   // image, e4m3 (x128)
__device__ uint8_t g_B8[(size_t)BDIM * DDIM];   // text,  e4m3 (x128)

// ---------------------------------------------------------------------------
// Fast epilogue math: sim = exp(-T^-1 * sqrt(max(q,0))) with single-MUFU
// sqrt.approx (rel err ~1e-7, negligible vs fp8 path's 3e-5).
// ---------------------------------------------------------------------------
__device__ __forceinline__ float sim_of(float q) {
    float d;
    asm("sqrt.approx.f32 %0, %1;" : "=f"(d) : "f"(fmaxf(q, 0.0f)));
    return __expf(-INV_T * d);
}

// ---------------------------------------------------------------------------
// Kernel 1: fp32 -> e4m3 (scaled by 128) + fp32 exact squared norms.
// One row per warp (best measured variant). grid = (BDIM/8, 2), 256 threads.
// ---------------------------------------------------------------------------
__device__ __forceinline__ uint16_t f2_to_e4m3x2(float hi, float lo) {
    uint16_t d;
    asm("cvt.rn.satfinite.e4m3x2.f32 %0, %1, %2;" : "=h"(d) : "f"(hi), "f"(lo));
    return d;
}

__global__ void convert_norms_kernel(const float* __restrict__ img,
                                     const float* __restrict__ txt) {
    const int warp = threadIdx.x >> 5, lane = threadIdx.x & 31;
    const int row  = blockIdx.x * 8 + warp;
    const float* src;
    uint8_t* dst;
    float* nrm;
    if (blockIdx.y == 0) { src = img; dst = g_A8; nrm = g_img_sq; }
    else                 { src = txt; dst = g_B8; nrm = g_txt_sq; }

    const float4* p = reinterpret_cast<const float4*>(src + (size_t)row * DDIM);
    uint32_t* q = reinterpret_cast<uint32_t*>(dst + (size_t)row * DDIM);

    float s = 0.0f;
    #pragma unroll
    for (int i = 0; i < 8; i++) {
        int f = i * 32 + lane;
        float4 v = p[f];
        s += v.x * v.x + v.y * v.y + v.z * v.z + v.w * v.w;
        uint16_t lo = f2_to_e4m3x2(v.y * 128.0f, v.x * 128.0f);
        uint16_t hi = f2_to_e4m3x2(v.w * 128.0f, v.z * 128.0f);
        q[f] = (uint32_t)lo | ((uint32_t)hi << 16);
    }
    #pragma unroll
    for (int m = 16; m > 0; m >>= 1) s += __shfl_xor_sync(0xffffffffu, s, m);
    if (lane == 0) nrm[row] = s;
}

// ---------------------------------------------------------------------------
// Kernel 2: e4m3 mma.sync m16n8k32 GEMM (champion R14 configuration).
// 128x128 CTA tile, 4 warps of 64x64, KT=128, 3-stage cp.async pipeline
// (fully unrolled loader — unroll-1 variant measured slower), XOR-swizzled
// 128B rows, fused sim epilogue with sqrt.approx.
// ---------------------------------------------------------------------------
__device__ __forceinline__ void load_stage(uint8_t* smem, int stage,
                                           int kt, int row0, int col0, int tid) {
    uint8_t* as = smem + (size_t)stage * STG_BYTES;
    uint8_t* bs = as + 128 * 128;
    #pragma unroll
    for (int l = 0; l < 8; l++) {
        const int id = tid + l * 128;        // 0..1023
        const int r  = id >> 3;              // tile row 0..127
        const int ch = id & 7;               // logical 16B chunk 0..7
        const int ph = ch ^ (r & 7);         // swizzled chunk
        uint32_t da = (uint32_t)__cvta_generic_to_shared(&as[r * 128 + ph * 16]);
        const void* ga = g_A8 + (size_t)(row0 + r) * DDIM + kt + ch * 16;
        asm volatile("cp.async.cg.shared.global [%0], [%1], 16;\n"
                     :: "r"(da), "l"(ga));
        uint32_t db = (uint32_t)__cvta_generic_to_shared(&bs[r * 128 + ph * 16]);
        const void* gb = g_B8 + (size_t)(col0 + r) * DDIM + kt + ch * 16;
        asm volatile("cp.async.cg.shared.global [%0], [%1], 16;\n"
                     :: "r"(db), "l"(gb));
    }
    asm volatile("cp.async.commit_group;\n" ::: "memory");
}

__global__ __launch_bounds__(128, 2)
void mma_sim_kernel() {
    extern __shared__ uint8_t smem[];
    __shared__ float s_isq[128];
    __shared__ float s_tsq[128];
    __shared__ float red[128][2];

    const int bj = blockIdx.x;
    const int bi = blockIdx.y;
    const int row0 = bi * 128;
    const int col0 = bj * 128;

    const int tid  = threadIdx.x;         // 0..127
    const int lane = tid & 31;
    const int warp = tid >> 5;            // 0..3
    const int wm   = warp >> 1;           // 0..1 (m)
    const int wn   = warp & 1;            // 0..1 (n)

    s_isq[tid] = g_img_sq[row0 + tid];
    s_tsq[tid] = g_txt_sq[col0 + tid];

    float acc[4][8][4];
    #pragma unroll
    for (int mf = 0; mf < 4; mf++)
        #pragma unroll
        for (int nf = 0; nf < 8; nf++)
            #pragma unroll
            for (int r = 0; r < 4; r++) acc[mf][nf][r] = 0.0f;

    // Prologue: fill 2 of 3 stages
    load_stage(smem, 0, 0, row0, col0, tid);
    load_stage(smem, 1, KT, row0, col0, tid);

    const int a_row = wm * 64 + (lane & 15);
    const int a_ch0 = (lane >> 4);
    const int b_row = wn * 64 + ((lane >> 4) << 3) + (lane & 7);
    const int b_ch0 = ((lane >> 3) & 1);

    int stg = 0;
    for (int it = 0; it < NK; it++) {
        if (it + 2 < NK)
            asm volatile("cp.async.wait_group 1;\n" ::: "memory");
        else
            asm volatile("cp.async.wait_group 0;\n" ::: "memory");
        __syncthreads();

        if (it + 2 < NK) {
            int nstg = stg + 2; if (nstg >= NSTG) nstg -= NSTG;
            load_stage(smem, nstg, (it + 2) * KT, row0, col0, tid);
        }

        const uint8_t* as = smem + (size_t)stg * STG_BYTES;
        const uint8_t* bs = as + 128 * 128;

        #pragma unroll
        for (int ks = 0; ks < 4; ks++) {      // four k32 steps per 128-fp8 stage
            uint32_t a[4][4], b[4][4];
            #pragma unroll
            for (int mf = 0; mf < 4; mf++) {
                int r  = a_row + mf * 16;
                int ph = (a_ch0 + ks * 2) ^ (r & 7);
                uint32_t addr = (uint32_t)__cvta_generic_to_shared(
                    &as[r * 128 + ph * 16]);
                asm volatile(
                    "ldmatrix.sync.aligned.m8n8.x4.shared.b16 "
                    "{%0,%1,%2,%3}, [%4];\n"
                    : "=r"(a[mf][0]), "=r"(a[mf][1]),
                      "=r"(a[mf][2]), "=r"(a[mf][3])
                    : "r"(addr));
            }
            #pragma unroll
            for (int p = 0; p < 4; p++) {
                int n  = b_row + p * 16;
                int ph = (b_ch0 + ks * 2) ^ (n & 7);
                uint32_t addr = (uint32_t)__cvta_generic_to_shared(
                    &bs[n * 128 + ph * 16]);
                asm volatile(
                    "ldmatrix.sync.aligned.m8n8.x4.shared.b16 "
                    "{%0,%1,%2,%3}, [%4];\n"
                    : "=r"(b[p][0]), "=r"(b[p][1]),
                      "=r"(b[p][2]), "=r"(b[p][3])
                    : "r"(addr));
            }
            #pragma unroll
            for (int mf = 0; mf < 4; mf++) {
                #pragma unroll
                for (int nf = 0; nf < 8; nf++) {
                    uint32_t b0 = b[nf >> 1][(nf & 1) * 2];
                    uint32_t b1 = b[nf >> 1][(nf & 1) * 2 + 1];
                    asm volatile(
                        "mma.sync.aligned.m16n8k32.row.col.f32.e4m3.e4m3.f32 "
                        "{%0,%1,%2,%3},{%4,%5,%6,%7},{%8,%9},{%0,%1,%2,%3};\n"
                        : "+f"(acc[mf][nf][0]), "+f"(acc[mf][nf][1]),
                          "+f"(acc[mf][nf][2]), "+f"(acc[mf][nf][3])
                        : "r"(a[mf][0]), "r"(a[mf][1]),
                          "r"(a[mf][2]), "r"(a[mf][3]),
                          "r"(b0), "r"(b1));
                }
            }
        }
        if (++stg >= NSTG) stg = 0;
    }

    // ---- fused epilogue: sim -> row partial sums + diagonal ----
    const bool diagblk = (bi == bj);
    #pragma unroll
    for (int mf = 0; mf < 4; mf++) {
        const int r_lo = wm * 64 + mf * 16 + (lane >> 2);
        const int r_hi = r_lo + 8;
        const float ia = s_isq[r_lo];
        const float ib = s_isq[r_hi];
        float s_lo = 0.0f, s_hi = 0.0f;

        #pragma unroll
        for (int nf = 0; nf < 8; nf++) {
            const int c0 = wn * 64 + nf * 8 + (lane & 3) * 2;
            const float t0 = s_tsq[c0];
            const float t1 = s_tsq[c0 + 1];
            float e00 = sim_of(fmaf(acc[mf][nf][0], -INV_S2, ia + t0));
            float e01 = sim_of(fmaf(acc[mf][nf][1], -INV_S2, ia + t1));
            float e10 = sim_of(fmaf(acc[mf][nf][2], -INV_S2, ib + t0));
            float e11 = sim_of(fmaf(acc[mf][nf][3], -INV_S2, ib + t1));
            s_lo += e00 + e01;
            s_hi += e10 + e11;
            if (diagblk) {
                if (r_lo == c0)     g_diag[row0 + r_lo] = e00;
                if (r_lo == c0 + 1) g_diag[row0 + r_lo] = e01;
                if (r_hi == c0)     g_diag[row0 + r_hi] = e10;
                if (r_hi == c0 + 1) g_diag[row0 + r_hi] = e11;
            }
        }
        s_lo += __shfl_xor_sync(0xffffffffu, s_lo, 1);
        s_lo += __shfl_xor_sync(0xffffffffu, s_lo, 2);
        s_hi += __shfl_xor_sync(0xffffffffu, s_hi, 1);
        s_hi += __shfl_xor_sync(0xffffffffu, s_hi, 2);
        if ((lane & 3) == 0) {
            red[r_lo][wn] = s_lo;
            red[r_hi][wn] = s_hi;
        }
    }
    __syncthreads();
    g_part[row0 + tid][bj] = red[tid][0] + red[tid][1];
}

// ---------------------------------------------------------------------------
// Kernel 3: fused loss. 32 blocks x 128 rows compute partials; the LAST
// block to finish (int counter only; all float sums fixed-order) reduces
// the 32 partials, writes output, resets counter for graph replay.
// ---------------------------------------------------------------------------
__global__ void loss_kernel(float* __restrict__ out) {
    const int tid = threadIdx.x;   // 128 threads
    const int row = blockIdx.x * 128 + tid;

    const float4* pr = reinterpret_cast<const float4*>(&g_part[row][0]);
    float rowsum = 0.0f;
    #pragma unroll
    for (int b = 0; b < NBLK / 4; b++) {
        float4 v = pr[b];
        rowsum += v.x + v.y + v.z + v.w;
    }
    float num = g_diag[row];
    float den = rowsum - num;
    float s = (den != 0.0f) ? (logf(den) - logf(num)) : 0.0f;

    #pragma unroll
    for (int m = 16; m > 0; m >>= 1) s += __shfl_xor_sync(0xffffffffu, s, m);
    __shared__ float red[4];
    __shared__ int s_last;
    if ((tid & 31) == 0) red[tid >> 5] = s;
    __syncthreads();
    if (tid == 0) {
        g_losspart[blockIdx.x] = red[0] + red[1] + red[2] + red[3];
        __threadfence();
        s_last = (atomicAdd(&g_cnt, 1) == 31);
    }
    __syncthreads();
    if (s_last && tid < 32) {
        float t = g_losspart[tid];
        #pragma unroll
        for (int m = 16; m > 0; m >>= 1) t += __shfl_xor_sync(0xffffffffu, t, m);
        if (tid == 0) { out[0] = t / (float)BDIM; g_cnt = 0; }
    }
}

// ---------------------------------------------------------------------------
// Launch. Inputs: d_in[0] = text_embeddings, d_in[1] = image_embeddings.
// ---------------------------------------------------------------------------
extern "C" void kernel_launch(void* const* d_in, const int* in_sizes, int n_in,
                              void* d_out, int out_size) {
    const float* txt = (const float*)d_in[0];
    const float* img = (const float*)d_in[1];
    float* out = (float*)d_out;

    cudaFuncSetAttribute(mma_sim_kernel,
                         cudaFuncAttributeMaxDynamicSharedMemorySize, DSMEM);

    dim3 cgrid(BDIM / 8, 2);
    convert_norms_kernel<<<cgrid, 256>>>(img, txt);

    dim3 ggrid(NBLK, NBLK);
    mma_sim_kernel<<<ggrid, 128, DSMEM>>>();

    loss_kernel<<<32, 128>>>(out);
}

// round 17
// speedup vs baseline: 1.0258x; 1.0073x over previous
#include <cuda_runtime.h>
#include <cuda_bf16.h>
#include <math.h>
#include <stdint.h>

// Problem constants (fixed: B=4096, D=1024)
#define BDIM 4096
#define DDIM 1024
#define INV_T 20.0f
#define NEG_INVT_LOG2E (-28.853900817779268f)   // -INV_T * log2(e), prescaled
#define NBLK 32                 // BDIM / 128 block-columns
#define KT 128                  // fp8 k elements per stage (128 B rows, swizzled)
#define NK (DDIM / KT)          // 8 k-tiles
#define NSTG 3                  // pipeline stages
#define STG_BYTES (2 * 128 * 128)            // A+B per stage = 32768 B
#define DSMEM (NSTG * STG_BYTES)             // 98304 B dynamic smem
#define INV_S2 (1.0f / 8192.0f)              // 2 / (128*128)

// Deterministic scratch (atomics only on an int completion counter)
__device__ float g_img_sq[BDIM];
__device__ float g_txt_sq[BDIM];
__device__ float g_diag[BDIM];
__device__ float g_part[BDIM][NBLK];
__device__ float g_losspart[32];
__device__ int   g_cnt;
__device__ uint8_t g_A8[(size_t)BDIM * DDIM];   // image, e4m3 (x128)
__device__ uint8_t g_B8[(size_t)BDIM * DDIM];   // text,  e4m3 (x128)

// ---------------------------------------------------------------------------
// Fast epilogue math: sim = exp(-T^-1 * sqrt(max(q,0)))
// = ex2(sqrt(q) * (-T^-1 * log2 e)). One MUFU sqrt + one mul + one MUFU ex2.
// ---------------------------------------------------------------------------
__device__ __forceinline__ float sim_of(float q) {
    float d, e;
    asm("sqrt.approx.f32 %0, %1;" : "=f"(d) : "f"(fmaxf(q, 0.0f)));
    asm("ex2.approx.f32 %0, %1;" : "=f"(e) : "f"(d * NEG_INVT_LOG2E));
    return e;
}

// ---------------------------------------------------------------------------
// Kernel 1: fp32 -> e4m3 (scaled by 128) + fp32 exact squared norms.
// One row per warp; ALL 8 float4 loads front-batched (MLP=8) before any
// convert/store so DRAM latency overlaps. grid = (BDIM/8, 2), 256 threads.
// ---------------------------------------------------------------------------
__device__ __forceinline__ uint16_t f2_to_e4m3x2(float hi, float lo) {
    uint16_t d;
    asm("cvt.rn.satfinite.e4m3x2.f32 %0, %1, %2;" : "=h"(d) : "f"(hi), "f"(lo));
    return d;
}

__global__ void convert_norms_kernel(const float* __restrict__ img,
                                     const float* __restrict__ txt) {
    const int warp = threadIdx.x >> 5, lane = threadIdx.x & 31;
    const int row  = blockIdx.x * 8 + warp;
    const float* src;
    uint8_t* dst;
    float* nrm;
    if (blockIdx.y == 0) { src = img; dst = g_A8; nrm = g_img_sq; }
    else                 { src = txt; dst = g_B8; nrm = g_txt_sq; }

    const float4* p = reinterpret_cast<const float4*>(src + (size_t)row * DDIM);
    uint32_t* q = reinterpret_cast<uint32_t*>(dst + (size_t)row * DDIM);

    float4 v[8];
    #pragma unroll
    for (int i = 0; i < 8; i++) v[i] = p[i * 32 + lane];   // 8 loads in flight

    float s = 0.0f;
    #pragma unroll
    for (int i = 0; i < 8; i++) {
        s += v[i].x * v[i].x + v[i].y * v[i].y
           + v[i].z * v[i].z + v[i].w * v[i].w;
        uint16_t lo = f2_to_e4m3x2(v[i].y * 128.0f, v[i].x * 128.0f);
        uint16_t hi = f2_to_e4m3x2(v[i].w * 128.0f, v[i].z * 128.0f);
        q[i * 32 + lane] = (uint32_t)lo | ((uint32_t)hi << 16);
    }
    #pragma unroll
    for (int m = 16; m > 0; m >>= 1) s += __shfl_xor_sync(0xffffffffu, s, m);
    if (lane == 0) nrm[row] = s;
}

// ---------------------------------------------------------------------------
// Kernel 2: e4m3 mma.sync m16n8k32 GEMM (champion R14 configuration).
// 128x128 CTA tile, 4 warps of 64x64, KT=128, 3-stage cp.async pipeline,
// XOR-swizzled 128B rows, fused sim epilogue with sqrt.approx + ex2.approx.
// ---------------------------------------------------------------------------
__device__ __forceinline__ void load_stage(uint8_t* smem, int stage,
                                           int kt, int row0, int col0, int tid) {
    uint8_t* as = smem + (size_t)stage * STG_BYTES;
    uint8_t* bs = as + 128 * 128;
    #pragma unroll
    for (int l = 0; l < 8; l++) {
        const int id = tid + l * 128;        // 0..1023
        const int r  = id >> 3;              // tile row 0..127
        const int ch = id & 7;               // logical 16B chunk 0..7
        const int ph = ch ^ (r & 7);         // swizzled chunk
        uint32_t da = (uint32_t)__cvta_generic_to_shared(&as[r * 128 + ph * 16]);
        const void* ga = g_A8 + (size_t)(row0 + r) * DDIM + kt + ch * 16;
        asm volatile("cp.async.cg.shared.global [%0], [%1], 16;\n"
                     :: "r"(da), "l"(ga));
        uint32_t db = (uint32_t)__cvta_generic_to_shared(&bs[r * 128 + ph * 16]);
        const void* gb = g_B8 + (size_t)(col0 + r) * DDIM + kt + ch * 16;
        asm volatile("cp.async.cg.shared.global [%0], [%1], 16;\n"
                     :: "r"(db), "l"(gb));
    }
    asm volatile("cp.async.commit_group;\n" ::: "memory");
}

__global__ __launch_bounds__(128, 2)
void mma_sim_kernel() {
    extern __shared__ uint8_t smem[];
    __shared__ float s_isq[128];
    __shared__ float s_tsq[128];
    __shared__ float red[128][2];

    const int bj = blockIdx.x;
    const int bi = blockIdx.y;
    const int row0 = bi * 128;
    const int col0 = bj * 128;

    const int tid  = threadIdx.x;         // 0..127
    const int lane = tid & 31;
    const int warp = tid >> 5;            // 0..3
    const int wm   = warp >> 1;           // 0..1 (m)
    const int wn   = warp & 1;            // 0..1 (n)

    s_isq[tid] = g_img_sq[row0 + tid];
    s_tsq[tid] = g_txt_sq[col0 + tid];

    float acc[4][8][4];
    #pragma unroll
    for (int mf = 0; mf < 4; mf++)
        #pragma unroll
        for (int nf = 0; nf < 8; nf++)
            #pragma unroll
            for (int r = 0; r < 4; r++) acc[mf][nf][r] = 0.0f;

    // Prologue: fill 2 of 3 stages
    load_stage(smem, 0, 0, row0, col0, tid);
    load_stage(smem, 1, KT, row0, col0, tid);

    const int a_row = wm * 64 + (lane & 15);
    const int a_ch0 = (lane >> 4);
    const int b_row = wn * 64 + ((lane >> 4) << 3) + (lane & 7);
    const int b_ch0 = ((lane >> 3) & 1);

    int stg = 0;
    for (int it = 0; it < NK; it++) {
        if (it + 2 < NK)
            asm volatile("cp.async.wait_group 1;\n" ::: "memory");
        else
            asm volatile("cp.async.wait_group 0;\n" ::: "memory");
        __syncthreads();

        if (it + 2 < NK) {
            int nstg = stg + 2; if (nstg >= NSTG) nstg -= NSTG;
            load_stage(smem, nstg, (it + 2) * KT, row0, col0, tid);
        }

        const uint8_t* as = smem + (size_t)stg * STG_BYTES;
        const uint8_t* bs = as + 128 * 128;

        #pragma unroll
        for (int ks = 0; ks < 4; ks++) {      // four k32 steps per 128-fp8 stage
            uint32_t a[4][4], b[4][4];
            #pragma unroll
            for (int mf = 0; mf < 4; mf++) {
                int r  = a_row + mf * 16;
                int ph = (a_ch0 + ks * 2) ^ (r & 7);
                uint32_t addr = (uint32_t)__cvta_generic_to_shared(
                    &as[r * 128 + ph * 16]);
                asm volatile(
                    "ldmatrix.sync.aligned.m8n8.x4.shared.b16 "
                    "{%0,%1,%2,%3}, [%4];\n"
                    : "=r"(a[mf][0]), "=r"(a[mf][1]),
                      "=r"(a[mf][2]), "=r"(a[mf][3])
                    : "r"(addr));
            }
            #pragma unroll
            for (int p = 0; p < 4; p++) {
                int n  = b_row + p * 16;
                int ph = (b_ch0 + ks * 2) ^ (n & 7);
                uint32_t addr = (uint32_t)__cvta_generic_to_shared(
                    &bs[n * 128 + ph * 16]);
                asm volatile(
                    "ldmatrix.sync.aligned.m8n8.x4.shared.b16 "
                    "{%0,%1,%2,%3}, [%4];\n"
                    : "=r"(b[p][0]), "=r"(b[p][1]),
                      "=r"(b[p][2]), "=r"(b[p][3])
                    : "r"(addr));
            }
            #pragma unroll
            for (int mf = 0; mf < 4; mf++) {
                #pragma unroll
                for (int nf = 0; nf < 8; nf++) {
                    uint32_t b0 = b[nf >> 1][(nf & 1) * 2];
                    uint32_t b1 = b[nf >> 1][(nf & 1) * 2 + 1];
                    asm volatile(
                        "mma.sync.aligned.m16n8k32.row.col.f32.e4m3.e4m3.f32 "
                        "{%0,%1,%2,%3},{%4,%5,%6,%7},{%8,%9},{%0,%1,%2,%3};\n"
                        : "+f"(acc[mf][nf][0]), "+f"(acc[mf][nf][1]),
                          "+f"(acc[mf][nf][2]), "+f"(acc[mf][nf][3])
                        : "r"(a[mf][0]), "r"(a[mf][1]),
                          "r"(a[mf][2]), "r"(a[mf][3]),
                          "r"(b0), "r"(b1));
                }
            }
        }
        if (++stg >= NSTG) stg = 0;
    }

    // ---- fused epilogue: sim -> row partial sums + diagonal ----
    const bool diagblk = (bi == bj);
    #pragma unroll
    for (int mf = 0; mf < 4; mf++) {
        const int r_lo = wm * 64 + mf * 16 + (lane >> 2);
        const int r_hi = r_lo + 8;
        const float ia = s_isq[r_lo];
        const float ib = s_isq[r_hi];
        float s_lo = 0.0f, s_hi = 0.0f;

        #pragma unroll
        for (int nf = 0; nf < 8; nf++) {
            const int c0 = wn * 64 + nf * 8 + (lane & 3) * 2;
            const float t0 = s_tsq[c0];
            const float t1 = s_tsq[c0 + 1];
            float e00 = sim_of(fmaf(acc[mf][nf][0], -INV_S2, ia + t0));
            float e01 = sim_of(fmaf(acc[mf][nf][1], -INV_S2, ia + t1));
            float e10 = sim_of(fmaf(acc[mf][nf][2], -INV_S2, ib + t0));
            float e11 = sim_of(fmaf(acc[mf][nf][3], -INV_S2, ib + t1));
            s_lo += e00 + e01;
            s_hi += e10 + e11;
            if (diagblk) {
                if (r_lo == c0)     g_diag[row0 + r_lo] = e00;
                if (r_lo == c0 + 1) g_diag[row0 + r_lo] = e01;
                if (r_hi == c0)     g_diag[row0 + r_hi] = e10;
                if (r_hi == c0 + 1) g_diag[row0 + r_hi] = e11;
            }
        }
        s_lo += __shfl_xor_sync(0xffffffffu, s_lo, 1);
        s_lo += __shfl_xor_sync(0xffffffffu, s_lo, 2);
        s_hi += __shfl_xor_sync(0xffffffffu, s_hi, 1);
        s_hi += __shfl_xor_sync(0xffffffffu, s_hi, 2);
        if ((lane & 3) == 0) {
            red[r_lo][wn] = s_lo;
            red[r_hi][wn] = s_hi;
        }
    }
    __syncthreads();
    g_part[row0 + tid][bj] = red[tid][0] + red[tid][1];
}

// ---------------------------------------------------------------------------
// Kernel 3: fused loss. 32 blocks x 128 rows compute partials; the LAST
// block to finish (int counter only; all float sums fixed-order) reduces
// the 32 partials, writes output, resets counter for graph replay.
// ---------------------------------------------------------------------------
__global__ void loss_kernel(float* __restrict__ out) {
    const int tid = threadIdx.x;   // 128 threads
    const int row = blockIdx.x * 128 + tid;

    const float4* pr = reinterpret_cast<const float4*>(&g_part[row][0]);
    float rowsum = 0.0f;
    #pragma unroll
    for (int b = 0; b < NBLK / 4; b++) {
        float4 v = pr[b];
        rowsum += v.x + v.y + v.z + v.w;
    }
    float num = g_diag[row];
    float den = rowsum - num;
    float s = (den != 0.0f) ? (logf(den) - logf(num)) : 0.0f;

    #pragma unroll
    for (int m = 16; m > 0; m >>= 1) s += __shfl_xor_sync(0xffffffffu, s, m);
    __shared__ float red[4];
    __shared__ int s_last;
    if ((tid & 31) == 0) red[tid >> 5] = s;
    __syncthreads();
    if (tid == 0) {
        g_losspart[blockIdx.x] = red[0] + red[1] + red[2] + red[3];
        __threadfence();
        s_last = (atomicAdd(&g_cnt, 1) == 31);
    }
    __syncthreads();
    if (s_last && tid < 32) {
        float t = g_losspart[tid];
        #pragma unroll
        for (int m = 16; m > 0; m >>= 1) t += __shfl_xor_sync(0xffffffffu, t, m);
        if (tid == 0) { out[0] = t / (float)BDIM; g_cnt = 0; }
    }
}

// ---------------------------------------------------------------------------
// Launch. Inputs: d_in[0] = text_embeddings, d_in[1] = image_embeddings.
// ---------------------------------------------------------------------------
extern "C" void kernel_launch(void* const* d_in, const int* in_sizes, int n_in,
                              void* d_out, int out_size) {
    const float* txt = (const float*)d_in[0];
    const float* img = (const float*)d_in[1];
    float* out = (float*)d_out;

    cudaFuncSetAttribute(mma_sim_kernel,
                         cudaFuncAttributeMaxDynamicSharedMemorySize, DSMEM);

    dim3 cgrid(BDIM / 8, 2);
    convert_norms_kernel<<<cgrid, 256>>>(img, txt);

    dim3 ggrid(NBLK, NBLK);
    mma_sim_kernel<<<ggrid, 128, DSMEM>>>();

    loss_kernel<<<32, 128>>>(out);
}